// round 4
// baseline (speedup 1.0000x reference)
#include <cuda_runtime.h>
#include <math.h>

#define H 1024
#define V 50257
#define S 4096
#define NLSE 128
#define CPART 64
#define RPB 8   // logits rows per block

// ---------------- scratch (device globals; no allocation allowed) ----------
__device__ float g_hnew[H];
__device__ float g_scores[S];
__device__ float g_attn[S];
__device__ float g_context[H];
__device__ float g_ctx_part[CPART * H];
__device__ float g_logits[V];
__device__ float g_lse_m[NLSE];
__device__ float g_lse_s[NLSE];

// ---------------- helpers --------------------------------------------------
__device__ __forceinline__ float dot4(float4 a, float4 b) {
    return a.x * b.x + a.y * b.y + a.z * b.z + a.w * b.w;
}
__device__ __forceinline__ float warp_sum(float v) {
    #pragma unroll
    for (int o = 16; o > 0; o >>= 1) v += __shfl_xor_sync(0xffffffffu, v, o);
    return v;
}
__device__ __forceinline__ float warp_max(float v) {
    #pragma unroll
    for (int o = 16; o > 0; o >>= 1) v = fmaxf(v, __shfl_xor_sync(0xffffffffu, v, o));
    return v;
}

// ---------------- K1: fused GRU cell. 1024 blocks x 256 threads ------------
__global__ void gru_kernel(const int* __restrict__ word,
                           const float* __restrict__ last_ctx,
                           const float* __restrict__ last_h,
                           const float* __restrict__ emb,
                           const float* __restrict__ w_ih,
                           const float* __restrict__ w_hh,
                           const float* __restrict__ b_ih,
                           const float* __restrict__ b_hh,
                           float* __restrict__ d_out) {
    const int j = blockIdx.x;
    const int tid = threadIdx.x;

    const float4* e4 = (const float4*)(emb + (size_t)word[0] * H);
    const float4* c4 = (const float4*)last_ctx;
    const float4* h4 = (const float4*)last_h;
    const float4* wr = (const float4*)(w_ih + (size_t)(j)        * 2 * H);
    const float4* wz = (const float4*)(w_ih + (size_t)(j + H)    * 2 * H);
    const float4* wn = (const float4*)(w_ih + (size_t)(j + 2*H)  * 2 * H);
    const float4* ur = (const float4*)(w_hh + (size_t)(j)        * H);
    const float4* uz = (const float4*)(w_hh + (size_t)(j + H)    * H);
    const float4* un = (const float4*)(w_hh + (size_t)(j + 2*H)  * H);

    float ar = 0.f, az = 0.f, an = 0.f, br = 0.f, bz = 0.f, bn = 0.f;

    #pragma unroll
    for (int k = 0; k < 2; k++) {
        int c = tid + 256 * k;
        float4 x = (c < 256) ? e4[c] : c4[c - 256];
        ar += dot4(wr[c], x);
        az += dot4(wz[c], x);
        an += dot4(wn[c], x);
    }
    {
        int c = tid;
        float4 hh = h4[c];
        br += dot4(ur[c], hh);
        bz += dot4(uz[c], hh);
        bn += dot4(un[c], hh);
    }

    ar = warp_sum(ar); az = warp_sum(az); an = warp_sum(an);
    br = warp_sum(br); bz = warp_sum(bz); bn = warp_sum(bn);

    __shared__ float red[6][8];
    int w = tid >> 5, l = tid & 31;
    if (l == 0) {
        red[0][w] = ar; red[1][w] = az; red[2][w] = an;
        red[3][w] = br; red[4][w] = bz; red[5][w] = bn;
    }
    __syncthreads();
    if (tid == 0) {
        float s[6];
        #pragma unroll
        for (int k = 0; k < 6; k++) {
            float acc = red[k][0];
            #pragma unroll
            for (int q = 1; q < 8; q++) acc += red[k][q];
            s[k] = acc;
        }
        float ir = s[0] + b_ih[j];
        float iz = s[1] + b_ih[j + H];
        float in_ = s[2] + b_ih[j + 2 * H];
        float hr = s[3] + b_hh[j];
        float hz = s[4] + b_hh[j + H];
        float hn = s[5] + b_hh[j + 2 * H];
        float r = 1.f / (1.f + expf(-(ir + hr)));
        float z = 1.f / (1.f + expf(-(iz + hz)));
        float n = tanhf(in_ + r * hn);
        float hv = last_h[j];
        float hnew = (1.f - z) * n + z * hv;
        g_hnew[j] = hnew;
        d_out[V + H + j] = hnew;   // h_new slot
    }
}

// ---------------- K2: scores[s] = enc[s] . h_new. 4096 blocks x 64 --------
__global__ void __launch_bounds__(64) scores_kernel(const float* __restrict__ enc) {
    const int s = blockIdx.x;
    const int tid = threadIdx.x;
    const float4* e4 = (const float4*)(enc + (size_t)s * H);
    const float4* h4 = (const float4*)g_hnew;
    float acc = 0.f;
    #pragma unroll
    for (int k = 0; k < 4; k++) {
        int c = tid + 64 * k;
        acc += dot4(e4[c], h4[c]);
    }
    acc = warp_sum(acc);
    __shared__ float red[2];
    if ((tid & 31) == 0) red[tid >> 5] = acc;
    __syncthreads();
    if (tid == 0) g_scores[s] = red[0] + red[1];
}

// ---------------- K3: softmax over 4096. 1 block x 1024 -------------------
__global__ void softmax_kernel(float* __restrict__ d_out) {
    const int tid = threadIdx.x;
    float v0 = g_scores[tid];
    float v1 = g_scores[tid + 1024];
    float v2 = g_scores[tid + 2048];
    float v3 = g_scores[tid + 3072];
    float m = fmaxf(fmaxf(v0, v1), fmaxf(v2, v3));

    __shared__ float sm[32];
    m = warp_max(m);
    if ((tid & 31) == 0) sm[tid >> 5] = m;
    __syncthreads();
    if (tid < 32) { float t = sm[tid]; t = warp_max(t); if (tid == 0) sm[0] = t; }
    __syncthreads();
    m = sm[0];

    float e0 = expf(v0 - m), e1 = expf(v1 - m), e2 = expf(v2 - m), e3 = expf(v3 - m);
    float ssum = e0 + e1 + e2 + e3;
    __shared__ float ss[32];
    ssum = warp_sum(ssum);
    if ((tid & 31) == 0) ss[tid >> 5] = ssum;
    __syncthreads();
    if (tid < 32) { float t = ss[tid]; t = warp_sum(t); if (tid == 0) ss[0] = t; }
    __syncthreads();
    float inv = 1.f / ss[0];

    float a0 = e0 * inv, a1 = e1 * inv, a2 = e2 * inv, a3 = e3 * inv;
    g_attn[tid]        = a0;  d_out[V + 2 * H + tid]        = a0;
    g_attn[tid + 1024] = a1;  d_out[V + 2 * H + tid + 1024] = a1;
    g_attn[tid + 2048] = a2;  d_out[V + 2 * H + tid + 2048] = a2;
    g_attn[tid + 3072] = a3;  d_out[V + 2 * H + tid + 3072] = a3;
}

// ---------------- K4a: context partials. CPART blocks x 256, NO atomics ---
__global__ void __launch_bounds__(256) ctx_partial_kernel(const float* __restrict__ enc) {
    const int b = blockIdx.x;
    const int d4 = threadIdx.x;                       // [0,256)
    const int s0 = b * (S / CPART);                   // 64 rows per block
    const float4* e4 = (const float4*)enc;
    float4 acc = make_float4(0.f, 0.f, 0.f, 0.f);
    #pragma unroll 8
    for (int s = s0; s < s0 + S / CPART; s++) {
        float a = g_attn[s];
        float4 e = e4[(size_t)s * 256 + d4];
        acc.x += a * e.x; acc.y += a * e.y; acc.z += a * e.z; acc.w += a * e.w;
    }
    ((float4*)g_ctx_part)[b * 256 + d4] = acc;
}

// ---------------- K4b: reduce partials -> context. 4 blocks x 256 ---------
__global__ void __launch_bounds__(256) ctx_reduce_kernel(float* __restrict__ d_out) {
    const int d = blockIdx.x * 256 + threadIdx.x;     // [0,1024)
    float s = 0.f;
    #pragma unroll 8
    for (int c = 0; c < CPART; c++) s += g_ctx_part[c * H + d];
    g_context[d] = s;
    d_out[V + d] = s;                                  // context slot
}

// ---------------- K5: logits. 8 rows/block, x staged in smem --------------
// grid ceil(V/8) x 256. Warp w handles row blockIdx.x*8+w: 16 float4 loads
// of out_w per lane, x from smem, warp-only reduction.
__global__ void __launch_bounds__(256) logits_kernel(const float* __restrict__ out_w,
                                                     const float* __restrict__ out_b) {
    __shared__ float4 xs[512];
    const int tid = threadIdx.x;

    // stage x = [h_new | context] (2048 floats = 512 float4)
    {
        const float4* h4 = (const float4*)g_hnew;
        const float4* c4 = (const float4*)g_context;
        int c0 = tid;
        int c1 = tid + 256;
        xs[c0] = h4[c0];
        xs[c1] = c4[c1 - 256];
    }
    __syncthreads();

    const int warp = tid >> 5;
    const int lane = tid & 31;
    const int row = blockIdx.x * RPB + warp;
    if (row >= V) return;

    const float4* w4 = (const float4*)(out_w + (size_t)row * 2 * H);
    float a0 = 0.f, a1 = 0.f, a2 = 0.f, a3 = 0.f;
    #pragma unroll
    for (int k = 0; k < 16; k += 4) {
        a0 += dot4(w4[lane + 32 * (k + 0)], xs[lane + 32 * (k + 0)]);
        a1 += dot4(w4[lane + 32 * (k + 1)], xs[lane + 32 * (k + 1)]);
        a2 += dot4(w4[lane + 32 * (k + 2)], xs[lane + 32 * (k + 2)]);
        a3 += dot4(w4[lane + 32 * (k + 3)], xs[lane + 32 * (k + 3)]);
    }
    float acc = warp_sum((a0 + a1) + (a2 + a3));
    if (lane == 0) g_logits[row] = acc + out_b[row];
}

// ---------------- K6: blockwise online logsumexp partials. 128 x 256 ------
__global__ void lse_partial_kernel() {
    const int b = blockIdx.x;
    const int tid = threadIdx.x;
    const int chunk = (V + NLSE - 1) / NLSE;            // 393
    const int lo = b * chunk;
    const int hi = min(lo + chunk, V);

    float m = -INFINITY, s = 0.f;
    for (int i = lo + tid; i < hi; i += 256) {
        float x = g_logits[i];
        float nm = fmaxf(m, x);
        s = s * expf(m - nm) + expf(x - nm);
        m = nm;
    }
    #pragma unroll
    for (int o = 16; o > 0; o >>= 1) {
        float om = __shfl_xor_sync(0xffffffffu, m, o);
        float os = __shfl_xor_sync(0xffffffffu, s, o);
        float nm = fmaxf(m, om);
        s = s * expf(m - nm) + os * expf(om - nm);
        m = nm;
    }
    __shared__ float shm[8], shs[8];
    if ((tid & 31) == 0) { shm[tid >> 5] = m; shs[tid >> 5] = s; }
    __syncthreads();
    if (tid == 0) {
        float mm = shm[0], sacc = shs[0];
        #pragma unroll
        for (int k = 1; k < 8; k++) {
            float om = shm[k], os = shs[k];
            float nm = fmaxf(mm, om);
            sacc = sacc * expf(mm - nm) + os * expf(om - nm);
            mm = nm;
        }
        g_lse_m[b] = mm;
        g_lse_s[b] = sacc;
    }
}

// ---------------- K7: final log-softmax write. ceil(V/256) x 256 ----------
__global__ void write_output_kernel(float* __restrict__ d_out) {
    float m = -INFINITY, s = 0.f;
    #pragma unroll 1
    for (int k = 0; k < NLSE; k++) {
        float om = g_lse_m[k], os = g_lse_s[k];
        float nm = fmaxf(m, om);
        s = s * expf(m - nm) + os * expf(om - nm);
        m = nm;
    }
    float logz = m + logf(s);
    int v = blockIdx.x * 256 + threadIdx.x;
    if (v < V) d_out[v] = g_logits[v] - logz;
}

// ---------------- launch ---------------------------------------------------
extern "C" void kernel_launch(void* const* d_in, const int* in_sizes, int n_in,
                              void* d_out, int out_size) {
    const int*   word     = (const int*)  d_in[0];
    const float* last_ctx = (const float*)d_in[1];
    const float* last_h   = (const float*)d_in[2];
    const float* enc      = (const float*)d_in[3];
    const float* emb      = (const float*)d_in[4];
    const float* w_ih     = (const float*)d_in[5];
    const float* w_hh     = (const float*)d_in[6];
    const float* b_ih     = (const float*)d_in[7];
    const float* b_hh     = (const float*)d_in[8];
    const float* out_w    = (const float*)d_in[9];
    const float* out_b    = (const float*)d_in[10];
    float* out = (float*)d_out;

    gru_kernel<<<H, 256>>>(word, last_ctx, last_h, emb, w_ih, w_hh, b_ih, b_hh, out);
    scores_kernel<<<S, 64>>>(enc);
    softmax_kernel<<<1, 1024>>>(out);
    ctx_partial_kernel<<<CPART, 256>>>(enc);
    ctx_reduce_kernel<<<4, 256>>>(out);
    logits_kernel<<<(V + RPB - 1) / RPB, 256>>>(out_w, out_b);
    lse_partial_kernel<<<NLSE, 256>>>();
    write_output_kernel<<<(V + 255) / 256, 256>>>(out);
}

// round 5
// speedup vs baseline: 1.0170x; 1.0170x over previous
#include <cuda_runtime.h>
#include <math.h>

#define H 1024
#define V 50257
#define S 4096
#define NLSE 128
#define CPART 256

// ---------------- scratch (device globals; no allocation allowed) ----------
__device__ float g_hnew[H];
__device__ float g_scores[S];
__device__ float g_attn[S];
__device__ float g_context[H];
__device__ float g_ctx_part[CPART * H];
__device__ float g_logits[V];
__device__ float g_lse_m[NLSE];
__device__ float g_lse_s[NLSE];

// ---------------- helpers --------------------------------------------------
__device__ __forceinline__ float dot4(float4 a, float4 b) {
    return a.x * b.x + a.y * b.y + a.z * b.z + a.w * b.w;
}
__device__ __forceinline__ float warp_sum(float v) {
    #pragma unroll
    for (int o = 16; o > 0; o >>= 1) v += __shfl_xor_sync(0xffffffffu, v, o);
    return v;
}
__device__ __forceinline__ float warp_max(float v) {
    #pragma unroll
    for (int o = 16; o > 0; o >>= 1) v = fmaxf(v, __shfl_xor_sync(0xffffffffu, v, o));
    return v;
}

// ---------------- K1: fused GRU cell. 1024 blocks x 256 threads ------------
__global__ void gru_kernel(const int* __restrict__ word,
                           const float* __restrict__ last_ctx,
                           const float* __restrict__ last_h,
                           const float* __restrict__ emb,
                           const float* __restrict__ w_ih,
                           const float* __restrict__ w_hh,
                           const float* __restrict__ b_ih,
                           const float* __restrict__ b_hh,
                           float* __restrict__ d_out) {
    const int j = blockIdx.x;
    const int tid = threadIdx.x;

    const float4* e4 = (const float4*)(emb + (size_t)word[0] * H);
    const float4* c4 = (const float4*)last_ctx;
    const float4* h4 = (const float4*)last_h;
    const float4* wr = (const float4*)(w_ih + (size_t)(j)        * 2 * H);
    const float4* wz = (const float4*)(w_ih + (size_t)(j + H)    * 2 * H);
    const float4* wn = (const float4*)(w_ih + (size_t)(j + 2*H)  * 2 * H);
    const float4* ur = (const float4*)(w_hh + (size_t)(j)        * H);
    const float4* uz = (const float4*)(w_hh + (size_t)(j + H)    * H);
    const float4* un = (const float4*)(w_hh + (size_t)(j + 2*H)  * H);

    float ar = 0.f, az = 0.f, an = 0.f, br = 0.f, bz = 0.f, bn = 0.f;

    #pragma unroll
    for (int k = 0; k < 2; k++) {
        int c = tid + 256 * k;
        float4 x = (c < 256) ? e4[c] : c4[c - 256];
        ar += dot4(wr[c], x);
        az += dot4(wz[c], x);
        an += dot4(wn[c], x);
    }
    {
        int c = tid;
        float4 hh = h4[c];
        br += dot4(ur[c], hh);
        bz += dot4(uz[c], hh);
        bn += dot4(un[c], hh);
    }

    ar = warp_sum(ar); az = warp_sum(az); an = warp_sum(an);
    br = warp_sum(br); bz = warp_sum(bz); bn = warp_sum(bn);

    __shared__ float red[6][8];
    int w = tid >> 5, l = tid & 31;
    if (l == 0) {
        red[0][w] = ar; red[1][w] = az; red[2][w] = an;
        red[3][w] = br; red[4][w] = bz; red[5][w] = bn;
    }
    __syncthreads();
    if (tid == 0) {
        float s[6];
        #pragma unroll
        for (int k = 0; k < 6; k++) {
            float acc = red[k][0];
            #pragma unroll
            for (int q = 1; q < 8; q++) acc += red[k][q];
            s[k] = acc;
        }
        float ir = s[0] + b_ih[j];
        float iz = s[1] + b_ih[j + H];
        float in_ = s[2] + b_ih[j + 2 * H];
        float hr = s[3] + b_hh[j];
        float hz = s[4] + b_hh[j + H];
        float hn = s[5] + b_hh[j + 2 * H];
        float r = 1.f / (1.f + expf(-(ir + hr)));
        float z = 1.f / (1.f + expf(-(iz + hz)));
        float n = tanhf(in_ + r * hn);
        float hv = last_h[j];
        float hnew = (1.f - z) * n + z * hv;
        g_hnew[j] = hnew;
        d_out[V + H + j] = hnew;   // h_new slot
    }
}

// ---------------- K2: scores[s] = enc[s] . h_new. 4096 blocks x 64 --------
__global__ void __launch_bounds__(64) scores_kernel(const float* __restrict__ enc) {
    const int s = blockIdx.x;
    const int tid = threadIdx.x;
    const float4* e4 = (const float4*)(enc + (size_t)s * H);
    const float4* h4 = (const float4*)g_hnew;
    float acc = 0.f;
    #pragma unroll
    for (int k = 0; k < 4; k++) {
        int c = tid + 64 * k;
        acc += dot4(e4[c], h4[c]);
    }
    acc = warp_sum(acc);
    __shared__ float red[2];
    if ((tid & 31) == 0) red[tid >> 5] = acc;
    __syncthreads();
    if (tid == 0) g_scores[s] = red[0] + red[1];
}

// ---------------- K3: softmax over 4096. 1 block x 1024 -------------------
__global__ void softmax_kernel(float* __restrict__ d_out) {
    const int tid = threadIdx.x;
    float v0 = g_scores[tid];
    float v1 = g_scores[tid + 1024];
    float v2 = g_scores[tid + 2048];
    float v3 = g_scores[tid + 3072];
    float m = fmaxf(fmaxf(v0, v1), fmaxf(v2, v3));

    __shared__ float sm[32];
    m = warp_max(m);
    if ((tid & 31) == 0) sm[tid >> 5] = m;
    __syncthreads();
    if (tid < 32) { float t = sm[tid]; t = warp_max(t); if (tid == 0) sm[0] = t; }
    __syncthreads();
    m = sm[0];

    float e0 = expf(v0 - m), e1 = expf(v1 - m), e2 = expf(v2 - m), e3 = expf(v3 - m);
    float ssum = e0 + e1 + e2 + e3;
    __shared__ float ss[32];
    ssum = warp_sum(ssum);
    if ((tid & 31) == 0) ss[tid >> 5] = ssum;
    __syncthreads();
    if (tid < 32) { float t = ss[tid]; t = warp_sum(t); if (tid == 0) ss[0] = t; }
    __syncthreads();
    float inv = 1.f / ss[0];

    float a0 = e0 * inv, a1 = e1 * inv, a2 = e2 * inv, a3 = e3 * inv;
    g_attn[tid]        = a0;  d_out[V + 2 * H + tid]        = a0;
    g_attn[tid + 1024] = a1;  d_out[V + 2 * H + tid + 1024] = a1;
    g_attn[tid + 2048] = a2;  d_out[V + 2 * H + tid + 2048] = a2;
    g_attn[tid + 3072] = a3;  d_out[V + 2 * H + tid + 3072] = a3;
}

// ---------------- K4a: context partials. 256 blocks x 256, NO atomics -----
// block b sums rows [b*16, b*16+16) across all 256 float4 columns.
__global__ void __launch_bounds__(256) ctx_partial_kernel(const float* __restrict__ enc) {
    const int b = blockIdx.x;
    const int d4 = threadIdx.x;                       // [0,256)
    const int s0 = b * (S / CPART);                   // 16 rows per block
    const float4* e4 = (const float4*)enc;
    float4 acc = make_float4(0.f, 0.f, 0.f, 0.f);
    #pragma unroll
    for (int s = s0; s < s0 + S / CPART; s++) {
        float a = g_attn[s];
        float4 e = e4[(size_t)s * 256 + d4];
        acc.x += a * e.x; acc.y += a * e.y; acc.z += a * e.z; acc.w += a * e.w;
    }
    ((float4*)g_ctx_part)[b * 256 + d4] = acc;
}

// ---------------- K4b: reduce partials -> context. 4 blocks x 256 ---------
__global__ void __launch_bounds__(256) ctx_reduce_kernel(float* __restrict__ d_out) {
    const int d = blockIdx.x * 256 + threadIdx.x;     // [0,1024)
    float s0 = 0.f, s1 = 0.f, s2 = 0.f, s3 = 0.f;
    #pragma unroll 4
    for (int c = 0; c < CPART; c += 4) {
        s0 += g_ctx_part[(c + 0) * H + d];
        s1 += g_ctx_part[(c + 1) * H + d];
        s2 += g_ctx_part[(c + 2) * H + d];
        s3 += g_ctx_part[(c + 3) * H + d];
    }
    float s = (s0 + s1) + (s2 + s3);
    g_context[d] = s;
    d_out[V + d] = s;                                  // context slot
}

// ---------------- K5: logits = out_w @ [h_new, ctx] + out_b. V x 128 ------
__global__ void __launch_bounds__(128) logits_kernel(const float* __restrict__ out_w,
                                                     const float* __restrict__ out_b) {
    const int v = blockIdx.x;
    const int tid = threadIdx.x;
    const float4* w4 = (const float4*)(out_w + (size_t)v * 2 * H);
    const float4* h4 = (const float4*)g_hnew;
    const float4* c4 = (const float4*)g_context;
    float acc = 0.f;
    #pragma unroll
    for (int k = 0; k < 4; k++) {
        int c = tid + 128 * k;
        float4 x = (k < 2) ? h4[c] : c4[c - 256];
        acc += dot4(w4[c], x);
    }
    acc = warp_sum(acc);
    __shared__ float red[4];
    if ((tid & 31) == 0) red[tid >> 5] = acc;
    __syncthreads();
    if (tid == 0) g_logits[v] = red[0] + red[1] + red[2] + red[3] + out_b[v];
}

// ---------------- K6: blockwise online logsumexp partials. 128 x 256 ------
__global__ void lse_partial_kernel() {
    const int b = blockIdx.x;
    const int tid = threadIdx.x;
    const int chunk = (V + NLSE - 1) / NLSE;            // 393
    const int lo = b * chunk;
    const int hi = min(lo + chunk, V);

    float m = -INFINITY, s = 0.f;
    for (int i = lo + tid; i < hi; i += 256) {
        float x = g_logits[i];
        float nm = fmaxf(m, x);
        s = s * expf(m - nm) + expf(x - nm);
        m = nm;
    }
    #pragma unroll
    for (int o = 16; o > 0; o >>= 1) {
        float om = __shfl_xor_sync(0xffffffffu, m, o);
        float os = __shfl_xor_sync(0xffffffffu, s, o);
        float nm = fmaxf(m, om);
        s = s * expf(m - nm) + os * expf(om - nm);
        m = nm;
    }
    __shared__ float shm[8], shs[8];
    if ((tid & 31) == 0) { shm[tid >> 5] = m; shs[tid >> 5] = s; }
    __syncthreads();
    if (tid == 0) {
        float mm = shm[0], sacc = shs[0];
        #pragma unroll
        for (int k = 1; k < 8; k++) {
            float om = shm[k], os = shs[k];
            float nm = fmaxf(mm, om);
            sacc = sacc * expf(mm - nm) + os * expf(om - nm);
            mm = nm;
        }
        g_lse_m[b] = mm;
        g_lse_s[b] = sacc;
    }
}

// ---------------- K7: final log-softmax write. ceil(V/256) x 256 ----------
__global__ void write_output_kernel(float* __restrict__ d_out) {
    float m = -INFINITY, s = 0.f;
    #pragma unroll 1
    for (int k = 0; k < NLSE; k++) {
        float om = g_lse_m[k], os = g_lse_s[k];
        float nm = fmaxf(m, om);
        s = s * expf(m - nm) + os * expf(om - nm);
        m = nm;
    }
    float logz = m + logf(s);
    int v = blockIdx.x * 256 + threadIdx.x;
    if (v < V) d_out[v] = g_logits[v] - logz;
}

// ---------------- launch ---------------------------------------------------
extern "C" void kernel_launch(void* const* d_in, const int* in_sizes, int n_in,
                              void* d_out, int out_size) {
    const int*   word     = (const int*)  d_in[0];
    const float* last_ctx = (const float*)d_in[1];
    const float* last_h   = (const float*)d_in[2];
    const float* enc      = (const float*)d_in[3];
    const float* emb      = (const float*)d_in[4];
    const float* w_ih     = (const float*)d_in[5];
    const float* w_hh     = (const float*)d_in[6];
    const float* b_ih     = (const float*)d_in[7];
    const float* b_hh     = (const float*)d_in[8];
    const float* out_w    = (const float*)d_in[9];
    const float* out_b    = (const float*)d_in[10];
    float* out = (float*)d_out;

    gru_kernel<<<H, 256>>>(word, last_ctx, last_h, emb, w_ih, w_hh, b_ih, b_hh, out);
    scores_kernel<<<S, 64>>>(enc);
    softmax_kernel<<<1, 1024>>>(out);
    ctx_partial_kernel<<<CPART, 256>>>(enc);
    ctx_reduce_kernel<<<4, 256>>>(out);
    logits_kernel<<<V, 128>>>(out_w, out_b);
    lse_partial_kernel<<<NLSE, 256>>>();
    write_output_kernel<<<(V + 255) / 256, 256>>>(out);
}

// round 7
// speedup vs baseline: 1.2226x; 1.2022x over previous
#include <cuda_runtime.h>
#include <math.h>
#include <float.h>

#define H 1024
#define V 50257
#define S 4096
#define ABLK 256      // attention kernel blocks (16 rows each)
#define LBLK 197      // lse kernel blocks (256 logits each)

// ---------------- scratch (device globals; no allocation allowed) ----------
__device__ float g_hnew[H];
__device__ float g_context[H];
__device__ float g_bmax[ABLK];
__device__ float g_bsum[ABLK];
__device__ float g_ctx_part[ABLK * H];
__device__ float g_logits[V];
__device__ float g_lse_m[LBLK];
__device__ float g_lse_s[LBLK];
__device__ unsigned int g_bar1;
__device__ unsigned int g_bar2;

// ---------------- helpers --------------------------------------------------
__device__ __forceinline__ float dot4(float4 a, float4 b) {
    return a.x * b.x + a.y * b.y + a.z * b.z + a.w * b.w;
}
__device__ __forceinline__ float warp_sum(float v) {
    #pragma unroll
    for (int o = 16; o > 0; o >>= 1) v += __shfl_xor_sync(0xffffffffu, v, o);
    return v;
}
__device__ __forceinline__ float warp_max(float v) {
    #pragma unroll
    for (int o = 16; o > 0; o >>= 1) v = fmaxf(v, __shfl_xor_sync(0xffffffffu, v, o));
    return v;
}
// grid spin-barrier: one arriving thread per block, others park on __syncthreads
__device__ __forceinline__ void grid_bar(unsigned int* bar, unsigned int target) {
    __syncthreads();
    if (threadIdx.x == 0) {
        __threadfence();
        atomicAdd(bar, 1u);
        while (atomicAdd(bar, 0u) < target) __nanosleep(60);
    }
    __syncthreads();
    __threadfence();
}

// ---------------- K1: fused GRU cell. 1024 blocks x 256 threads ------------
__global__ void gru_kernel(const int* __restrict__ word,
                           const float* __restrict__ last_ctx,
                           const float* __restrict__ last_h,
                           const float* __restrict__ emb,
                           const float* __restrict__ w_ih,
                           const float* __restrict__ w_hh,
                           const float* __restrict__ b_ih,
                           const float* __restrict__ b_hh,
                           float* __restrict__ d_out) {
    const int j = blockIdx.x;
    const int tid = threadIdx.x;
    if (j == 0 && tid == 0) { g_bar1 = 0u; g_bar2 = 0u; }   // reset spin barriers

    const float4* e4 = (const float4*)(emb + (size_t)word[0] * H);
    const float4* c4 = (const float4*)last_ctx;
    const float4* h4 = (const float4*)last_h;
    const float4* wr = (const float4*)(w_ih + (size_t)(j)        * 2 * H);
    const float4* wz = (const float4*)(w_ih + (size_t)(j + H)    * 2 * H);
    const float4* wn = (const float4*)(w_ih + (size_t)(j + 2*H)  * 2 * H);
    const float4* ur = (const float4*)(w_hh + (size_t)(j)        * H);
    const float4* uz = (const float4*)(w_hh + (size_t)(j + H)    * H);
    const float4* un = (const float4*)(w_hh + (size_t)(j + 2*H)  * H);

    float ar = 0.f, az = 0.f, an = 0.f, br = 0.f, bz = 0.f, bn = 0.f;

    #pragma unroll
    for (int k = 0; k < 2; k++) {
        int c = tid + 256 * k;
        float4 x = (c < 256) ? e4[c] : c4[c - 256];
        ar += dot4(wr[c], x);
        az += dot4(wz[c], x);
        an += dot4(wn[c], x);
    }
    {
        int c = tid;
        float4 hh = h4[c];
        br += dot4(ur[c], hh);
        bz += dot4(uz[c], hh);
        bn += dot4(un[c], hh);
    }

    ar = warp_sum(ar); az = warp_sum(az); an = warp_sum(an);
    br = warp_sum(br); bz = warp_sum(bz); bn = warp_sum(bn);

    __shared__ float red[6][8];
    int w = tid >> 5, l = tid & 31;
    if (l == 0) {
        red[0][w] = ar; red[1][w] = az; red[2][w] = an;
        red[3][w] = br; red[4][w] = bz; red[5][w] = bn;
    }
    __syncthreads();
    if (tid == 0) {
        float s[6];
        #pragma unroll
        for (int k = 0; k < 6; k++) {
            float acc = red[k][0];
            #pragma unroll
            for (int q = 1; q < 8; q++) acc += red[k][q];
            s[k] = acc;
        }
        float ir = s[0] + b_ih[j];
        float iz = s[1] + b_ih[j + H];
        float in_ = s[2] + b_ih[j + 2 * H];
        float hr = s[3] + b_hh[j];
        float hz = s[4] + b_hh[j + H];
        float hn = s[5] + b_hh[j + 2 * H];
        float r = 1.f / (1.f + expf(-(ir + hr)));
        float z = 1.f / (1.f + expf(-(iz + hz)));
        float n = tanhf(in_ + r * hn);
        float hv = last_h[j];
        float hnew = (1.f - z) * n + z * hv;
        g_hnew[j] = hnew;
        d_out[V + H + j] = hnew;   // h_new slot
    }
}

// ---------------- K2: attention mega-kernel. ABLK=256 blocks x 256 --------
__global__ void __launch_bounds__(256) attention_kernel(const float* __restrict__ enc,
                                                        float* __restrict__ d_out) {
    const int b = blockIdx.x;
    const int tid = threadIdx.x;
    const int warp = tid >> 5, lane = tid & 31;
    const float4* enc4 = (const float4*)enc;
    const float4* h4 = (const float4*)g_hnew;

    __shared__ float sc[16];     // this block's 16 scores
    __shared__ float ev[16];     // exp(score - M)
    __shared__ float av[16];     // normalized attn
    __shared__ float r8[8];
    __shared__ float bc;         // broadcast slot

    // -------- P1: scores for rows [16b, 16b+16), warp w does rows 2w,2w+1
    #pragma unroll
    for (int rr = 0; rr < 2; rr++) {
        int local = warp * 2 + rr;
        const float4* e4 = enc4 + (size_t)(b * 16 + local) * 256;
        float a0 = 0.f, a1 = 0.f;
        #pragma unroll
        for (int k = 0; k < 8; k += 2) {
            a0 += dot4(e4[lane + 32 * k],       h4[lane + 32 * k]);
            a1 += dot4(e4[lane + 32 * (k + 1)], h4[lane + 32 * (k + 1)]);
        }
        float acc = warp_sum(a0 + a1);
        if (lane == 0) sc[local] = acc;
    }
    __syncthreads();
    if (tid < 32) {
        float v = (lane < 16) ? sc[lane] : -FLT_MAX;
        v = warp_max(v);
        if (lane == 0) g_bmax[b] = v;
    }
    grid_bar(&g_bar1, ABLK);

    // -------- P2: global max, exp, block partial sum
    {
        float v = __ldcg(&g_bmax[tid]);            // L2 load (cross-SM data)
        v = warp_max(v);
        if (lane == 0) r8[warp] = v;
        __syncthreads();
        if (tid == 0) {
            float m = r8[0];
            #pragma unroll
            for (int k = 1; k < 8; k++) m = fmaxf(m, r8[k]);
            bc = m;
        }
        __syncthreads();
        float M = bc;
        if (tid < 16) ev[tid] = expf(sc[tid] - M);
        __syncthreads();
        if (tid < 32) {
            float e = (lane < 16) ? ev[lane] : 0.f;
            e = warp_sum(e);
            if (lane == 0) g_bsum[b] = e;
        }
    }
    grid_bar(&g_bar1, 2 * ABLK);

    // -------- P3: normalize, write attn, ctx partial
    {
        float v = __ldcg(&g_bsum[tid]);
        v = warp_sum(v);
        __syncthreads();                           // r8 reuse guard
        if (lane == 0) r8[warp] = v;
        __syncthreads();
        if (tid == 0) {
            float z = r8[0];
            #pragma unroll
            for (int k = 1; k < 8; k++) z += r8[k];
            bc = 1.f / z;
        }
        __syncthreads();
        float invZ = bc;
        if (tid < 16) {
            float a = ev[tid] * invZ;
            av[tid] = a;
            d_out[V + 2 * H + b * 16 + tid] = a;   // attn slot
        }
        __syncthreads();
        const float4* e4 = enc4 + (size_t)(b * 16) * 256;
        float4 acc = make_float4(0.f, 0.f, 0.f, 0.f);
        #pragma unroll
        for (int i = 0; i < 16; i++) {
            float a = av[i];
            float4 e = e4[(size_t)i * 256 + tid];  // L1-hot from P1
            acc.x += a * e.x; acc.y += a * e.y; acc.z += a * e.z; acc.w += a * e.w;
        }
        ((float4*)g_ctx_part)[b * 256 + tid] = acc;
    }
    grid_bar(&g_bar1, 3 * ABLK);

    // -------- P4: ctx reduce — block b produces context[4b .. 4b+3]
    {
        float4 val = __ldcg(&((const float4*)g_ctx_part)[(size_t)tid * 256 + b]);
        val.x = warp_sum(val.x); val.y = warp_sum(val.y);
        val.z = warp_sum(val.z); val.w = warp_sum(val.w);
        __shared__ float4 r84[8];
        if (lane == 0) r84[warp] = val;
        __syncthreads();
        if (tid == 0) {
            float4 s = r84[0];
            #pragma unroll
            for (int k = 1; k < 8; k++) {
                s.x += r84[k].x; s.y += r84[k].y; s.z += r84[k].z; s.w += r84[k].w;
            }
            ((float4*)g_context)[b] = s;
            d_out[V + 4 * b + 0] = s.x;            // context slot
            d_out[V + 4 * b + 1] = s.y;
            d_out[V + 4 * b + 2] = s.z;
            d_out[V + 4 * b + 3] = s.w;
        }
    }
}

// ---------------- K3: logits = out_w @ [h_new, ctx] + out_b. V x 128 ------
__global__ void __launch_bounds__(128) logits_kernel(const float* __restrict__ out_w,
                                                     const float* __restrict__ out_b) {
    const int v = blockIdx.x;
    const int tid = threadIdx.x;
    const float4* w4 = (const float4*)(out_w + (size_t)v * 2 * H);
    const float4* h4 = (const float4*)g_hnew;
    const float4* c4 = (const float4*)g_context;
    float acc = 0.f;
    #pragma unroll
    for (int k = 0; k < 4; k++) {
        int c = tid + 128 * k;
        float4 x = (k < 2) ? h4[c] : c4[c - 256];
        acc += dot4(w4[c], x);
    }
    acc = warp_sum(acc);
    __shared__ float red[4];
    if ((tid & 31) == 0) red[tid >> 5] = acc;
    __syncthreads();
    if (tid == 0) g_logits[v] = red[0] + red[1] + red[2] + red[3] + out_b[v];
}

// ---------------- K4: fused logsumexp + write. LBLK=197 blocks x 256 ------
// NaN fix: pad with -FLT_MAX (finite) so (m - nm) never hits INF-INF.
__global__ void __launch_bounds__(256) lse_write_kernel(float* __restrict__ d_out) {
    const int b = blockIdx.x;
    const int tid = threadIdx.x;
    const int warp = tid >> 5, lane = tid & 31;
    const int v = b * 256 + tid;

    float m = (v < V) ? g_logits[v] : -FLT_MAX;
    float s = (v < V) ? 1.f : 0.f;
    #pragma unroll
    for (int o = 16; o > 0; o >>= 1) {
        float om = __shfl_xor_sync(0xffffffffu, m, o);
        float os = __shfl_xor_sync(0xffffffffu, s, o);
        float nm = fmaxf(m, om);
        s = s * expf(m - nm) + os * expf(om - nm);
        m = nm;
    }
    __shared__ float shm[8], shs[8];
    if (lane == 0) { shm[warp] = m; shs[warp] = s; }
    __syncthreads();
    if (tid == 0) {
        float mm = shm[0], sacc = shs[0];
        #pragma unroll
        for (int k = 1; k < 8; k++) {
            float om = shm[k], os = shs[k];
            float nm = fmaxf(mm, om);
            sacc = sacc * expf(mm - nm) + os * expf(om - nm);
            mm = nm;
        }
        g_lse_m[b] = mm;
        g_lse_s[b] = sacc;
    }
    grid_bar(&g_bar2, LBLK);

    // merge all LBLK partials (threads 0..LBLK-1 hold one each)
    float m2 = (tid < LBLK) ? __ldcg(&g_lse_m[tid]) : -FLT_MAX;
    float s2 = (tid < LBLK) ? __ldcg(&g_lse_s[tid]) : 0.f;
    #pragma unroll
    for (int o = 16; o > 0; o >>= 1) {
        float om = __shfl_xor_sync(0xffffffffu, m2, o);
        float os = __shfl_xor_sync(0xffffffffu, s2, o);
        float nm = fmaxf(m2, om);
        s2 = s2 * expf(m2 - nm) + os * expf(om - nm);
        m2 = nm;
    }
    __syncthreads();                 // reuse shm/shs
    if (lane == 0) { shm[warp] = m2; shs[warp] = s2; }
    __syncthreads();
    __shared__ float sz;
    if (tid == 0) {
        float mm = shm[0], sacc = shs[0];
        #pragma unroll
        for (int k = 1; k < 8; k++) {
            float om = shm[k], os = shs[k];
            float nm = fmaxf(mm, om);
            sacc = sacc * expf(mm - nm) + os * expf(om - nm);
            mm = nm;
        }
        sz = mm + logf(sacc);
    }
    __syncthreads();
    float logz = sz;
    if (v < V) d_out[v] = g_logits[v] - logz;
}

// ---------------- launch ---------------------------------------------------
extern "C" void kernel_launch(void* const* d_in, const int* in_sizes, int n_in,
                              void* d_out, int out_size) {
    const int*   word     = (const int*)  d_in[0];
    const float* last_ctx = (const float*)d_in[1];
    const float* last_h   = (const float*)d_in[2];
    const float* enc      = (const float*)d_in[3];
    const float* emb      = (const float*)d_in[4];
    const float* w_ih     = (const float*)d_in[5];
    const float* w_hh     = (const float*)d_in[6];
    const float* b_ih     = (const float*)d_in[7];
    const float* b_hh     = (const float*)d_in[8];
    const float* out_w    = (const float*)d_in[9];
    const float* out_b    = (const float*)d_in[10];
    float* out = (float*)d_out;

    gru_kernel<<<H, 256>>>(word, last_ctx, last_h, emb, w_ih, w_hh, b_ih, b_hh, out);
    attention_kernel<<<ABLK, 256>>>(enc, out);
    logits_kernel<<<V, 128>>>(out_w, out_b);
    lse_write_kernel<<<LBLK, 256>>>(out);
}